// round 4
// baseline (speedup 1.0000x reference)
#include <cuda_runtime.h>

#define BB 4
#define NN 16384
#define CC 64
#define KI 16
#define HH 8

// ---------------- fused kernel: q-projection + gather + factored attention ----------------
// warp per point; lane = 4*g + kq; lane holds nb[c=8g..8g+7][kk=4kq..4kq+3]
__global__ __launch_bounds__(256, 2) void attn_kernel(
    const float* __restrict__ pcd, const float* __restrict__ neighbors,
    const float* __restrict__ xyz,
    const float* __restrict__ Wq, const float* __restrict__ Wk,
    const float* __restrict__ Wv,
    const int* __restrict__ idx_all, float* __restrict__ out)
{
    extern __shared__ float sm[];
    float* WkT_s = sm;                    // [c][o], 67*68
    float* Wv_s  = WkT_s + 67 * 68;       // [o][c], 64*68
    float* WqT_s = Wv_s + 64 * 68;        // [c][o], 67*68
    float* qhW_s = WqT_s + 67 * 68;       // [pt][h*68 + c], 8*544
    float* q_s   = qhW_s + 8 * 544;       // [pt][o], 512
    float* out_s = q_s + 512;             // [pt][o], 512
    float* pcd_s = out_s + 512;           // [c][nn], 67*8 (pad 544)

    int t = threadIdx.x;
    for (int idx = t; idx < 64 * 67; idx += 256) {
        int o = idx / 67, c = idx % 67;
        WkT_s[c * 68 + o] = Wk[idx];
        Wv_s[o * 68 + c] = Wv[idx];
        WqT_s[c * 68 + o] = Wq[idx];
    }
    __syncthreads();

    const int pt = t >> 5, ln = t & 31, g = ln >> 2, kq = ln & 3;
    const int qo = t & 63, qp2 = t >> 6;          // q-projection mapping
    const int NTILE = (BB * NN) / 8;              // 8192

    for (int tile = blockIdx.x; tile < NTILE; tile += gridDim.x) {
        int b = (tile * 8) >> 14;
        int n0 = (tile * 8) & (NN - 1);

        // stage pcd_cat tile: pcd_s[c*8 + nn], c in [0,67)
        for (int idx = t; idx < 536; idx += 256) {
            int c = idx >> 3, nn = idx & 7;
            pcd_s[idx] = (c < 64) ? pcd[(b * 64 + c) * NN + n0 + nn]
                                  : xyz[(b * 3 + (c - 64)) * NN + n0 + nn];
        }
        __syncthreads();

        // q[pt][o] = sum_c Wq[o,c] * pcd_cat[c, n0+pt]; each thread does 2 pts
        {
            float a0 = 0.f, a1 = 0.f;
            const float* ps = pcd_s + 2 * qp2;
            #pragma unroll 4
            for (int c = 0; c < 67; c++) {
                float w = WqT_s[c * 68 + qo];
                a0 += w * ps[c * 8];
                a1 += w * ps[c * 8 + 1];
            }
            q_s[(2 * qp2) * 64 + qo] = a0;
            q_s[(2 * qp2 + 1) * 64 + qo] = a1;
        }
        __syncthreads();

        // qhW[h][c] = (1/sqrt(8)) * sum_d q[h*8+d] * Wk[h*8+d][c]
        {
            int h = ln & 7, c0 = ln >> 3;
            const float* qp = q_s + pt * 64 + h * 8;
            float4 qa = *(const float4*)qp;
            float4 qb = *(const float4*)(qp + 4);
            float* dst = qhW_s + pt * 544 + h * 68;
            for (int c = c0; c < 67; c += 4) {
                const float* wp = WkT_s + c * 68 + h * 8;
                float4 wa = *(const float4*)wp;
                float4 wb = *(const float4*)(wp + 4);
                float a = qa.x * wa.x + qa.y * wa.y + qa.z * wa.z + qa.w * wa.w
                        + qb.x * wb.x + qb.y * wb.y + qb.z * wb.z + qb.w * wb.w;
                dst[c] = a * 0.35355339059327373f;   // 1/sqrt(D)
            }
        }
        __syncwarp();

        int n = n0 + pt;

        // load neighbor block: 8 rows (c) x 4 cols (kk) per lane
        float4 nbv[8];
        {
            const float* nbase = neighbors + ((b * 64) * NN + n) * 16 + kq * 4;
            #pragma unroll
            for (int j = 0; j < 8; j++)
                nbv[j] = *(const float4*)(nbase + (g * 8 + j) * (NN * 16));
        }
        // gathered xyz: ONLY lanes 0-3 (g==0) need it; all consumers are g==0-closed
        float4 xr0 = make_float4(0.f, 0.f, 0.f, 0.f), xr1 = xr0, xr2 = xr0;
        if (ln < 4) {
            const int4 iv = *(const int4*)(idx_all + (b * NN + n) * 16 + ln * 4);
            const float* xb = xyz + b * 3 * NN;
            xr0 = make_float4(xb[iv.x], xb[iv.y], xb[iv.z], xb[iv.w]);
            xr1 = make_float4(xb[NN + iv.x], xb[NN + iv.y], xb[NN + iv.z], xb[NN + iv.w]);
            xr2 = make_float4(xb[2 * NN + iv.x], xb[2 * NN + iv.y], xb[2 * NN + iv.z], xb[2 * NN + iv.w]);
        }

        const float* qhWp = qhW_s + pt * 544;
        #pragma unroll 1
        for (int h = 0; h < 8; h++) {
            const float* qp = qhWp + h * 68;
            float4 qa = *(const float4*)(qp + g * 8);
            float4 qb = *(const float4*)(qp + g * 8 + 4);
            // energy partials over this lane's 8 channels
            float4 e = make_float4(0.f, 0.f, 0.f, 0.f);
            float qs[8] = {qa.x, qa.y, qa.z, qa.w, qb.x, qb.y, qb.z, qb.w};
            #pragma unroll
            for (int j = 0; j < 8; j++) {
                e.x += qs[j] * nbv[j].x; e.y += qs[j] * nbv[j].y;
                e.z += qs[j] * nbv[j].z; e.w += qs[j] * nbv[j].w;
            }
            if (g == 0) {   // xyz channels 64..66 counted once
                float4 qc = *(const float4*)(qp + 64);
                e.x += qc.x * xr0.x + qc.y * xr1.x + qc.z * xr2.x;
                e.y += qc.x * xr0.y + qc.y * xr1.y + qc.z * xr2.y;
                e.z += qc.x * xr0.z + qc.y * xr1.z + qc.z * xr2.z;
                e.w += qc.x * xr0.w + qc.y * xr1.w + qc.z * xr2.w;
            }
            // reduce over g (xor 4,8,16)
            #pragma unroll
            for (int m = 4; m <= 16; m <<= 1) {
                e.x += __shfl_xor_sync(0xffffffffu, e.x, m);
                e.y += __shfl_xor_sync(0xffffffffu, e.y, m);
                e.z += __shfl_xor_sync(0xffffffffu, e.z, m);
                e.w += __shfl_xor_sync(0xffffffffu, e.w, m);
            }
            // softmax over the 16 kk (kq covers groups; xor 1,2)
            float mx = fmaxf(fmaxf(e.x, e.y), fmaxf(e.z, e.w));
            mx = fmaxf(mx, __shfl_xor_sync(0xffffffffu, mx, 1));
            mx = fmaxf(mx, __shfl_xor_sync(0xffffffffu, mx, 2));
            float4 pr;
            pr.x = __expf(e.x - mx); pr.y = __expf(e.y - mx);
            pr.z = __expf(e.z - mx); pr.w = __expf(e.w - mx);
            float s = pr.x + pr.y + pr.z + pr.w;
            s += __shfl_xor_sync(0xffffffffu, s, 1);
            s += __shfl_xor_sync(0xffffffffu, s, 2);
            float inv = __fdividef(1.0f, s);
            pr.x *= inv; pr.y *= inv; pr.z *= inv; pr.w *= inv;

            // s[c] partials (dot of attn with this lane's 4 kk)
            float sp[8];
            #pragma unroll
            for (int j = 0; j < 8; j++)
                sp[j] = pr.x * nbv[j].x + pr.y * nbv[j].y + pr.z * nbv[j].z + pr.w * nbv[j].w;
            #pragma unroll
            for (int j = 0; j < 8; j++) {
                sp[j] += __shfl_xor_sync(0xffffffffu, sp[j], 1);
                sp[j] += __shfl_xor_sync(0xffffffffu, sp[j], 2);
            }
            // xyz-channel s values: only lanes 0-3 produce/consume (xor 1,2 closed there)
            float sx0 = pr.x * xr0.x + pr.y * xr0.y + pr.z * xr0.z + pr.w * xr0.w;
            float sx1 = pr.x * xr1.x + pr.y * xr1.y + pr.z * xr1.z + pr.w * xr1.w;
            float sx2 = pr.x * xr2.x + pr.y * xr2.y + pr.z * xr2.z + pr.w * xr2.w;
            sx0 += __shfl_xor_sync(0xffffffffu, sx0, 1);
            sx0 += __shfl_xor_sync(0xffffffffu, sx0, 2);
            sx1 += __shfl_xor_sync(0xffffffffu, sx1, 1);
            sx1 += __shfl_xor_sync(0xffffffffu, sx1, 2);
            sx2 += __shfl_xor_sync(0xffffffffu, sx2, 1);
            sx2 += __shfl_xor_sync(0xffffffffu, sx2, 2);

            // out[o] = sum_c Wv[o][c] * s[c]; kq picks d-pair, g picks c-chunk
            #pragma unroll
            for (int dd = 0; dd < 2; dd++) {
                int o = h * 8 + kq * 2 + dd;
                const float* wp = Wv_s + o * 68;
                float4 wa = *(const float4*)(wp + g * 8);
                float4 wb = *(const float4*)(wp + g * 8 + 4);
                float a = wa.x * sp[0] + wa.y * sp[1] + wa.z * sp[2] + wa.w * sp[3]
                        + wb.x * sp[4] + wb.y * sp[5] + wb.z * sp[6] + wb.w * sp[7];
                if (g == 0) {
                    float4 wc = *(const float4*)(wp + 64);
                    a += wc.x * sx0 + wc.y * sx1 + wc.z * sx2;
                }
                a += __shfl_xor_sync(0xffffffffu, a, 4);
                a += __shfl_xor_sync(0xffffffffu, a, 8);
                a += __shfl_xor_sync(0xffffffffu, a, 16);
                if (ln < 4) out_s[pt * 64 + o] = a;
            }
        }
        __syncthreads();
        // coalesced output: out[b][o][n]
        for (int idx = t; idx < 512; idx += 256) {
            int o = idx >> 3, lpt = idx & 7;
            out[(b * 64 + o) * NN + n0 + lpt] = out_s[lpt * 64 + o];
        }
        __syncthreads();
    }
}

extern "C" void kernel_launch(void* const* d_in, const int* in_sizes, int n_in,
                              void* d_out, int out_size) {
    const float* pcd       = (const float*)d_in[0];
    const float* neighbors = (const float*)d_in[1];
    const float* xyz       = (const float*)d_in[2];
    const float* Wq        = (const float*)d_in[3];
    const float* Wk        = (const float*)d_in[4];
    const float* Wv        = (const float*)d_in[5];
    const int*   idx_all   = (const int*)d_in[6];
    float* out = (float*)d_out;

    // floats: 3*weights(4556+4352+4556) + qhW 4352 + q 512 + out 512 + pcd 544
    const int smem = (67 * 68 + 64 * 68 + 67 * 68 + 8 * 544 + 512 + 512 + 544) * 4;
    cudaFuncSetAttribute(attn_kernel, cudaFuncAttributeMaxDynamicSharedMemorySize, smem);
    attn_kernel<<<304, 256, smem>>>(pcd, neighbors, xyz, Wq, Wk, Wv, idx_all, out);
}

// round 7
// speedup vs baseline: 1.0549x; 1.0549x over previous
#include <cuda_runtime.h>

#define BB 4
#define NN 16384
#define CC 64
#define KI 16
#define HH 8

// ---------------- fused kernel: q-projection + gather + factored attention ----------------
// warp per point; lane = 4*g + kq; lane holds nb[c=8g..8g+7][kk=4kq..4kq+3]
__global__ __launch_bounds__(256, 2) void attn_kernel(
    const float* __restrict__ pcd, const float* __restrict__ neighbors,
    const float* __restrict__ xyz,
    const float* __restrict__ Wq, const float* __restrict__ Wk,
    const float* __restrict__ Wv,
    const int* __restrict__ idx_all, float* __restrict__ out)
{
    extern __shared__ float sm[];
    float* WkT_s = sm;                    // [c][o], 67*68
    float* Wv_s  = WkT_s + 67 * 68;       // [o][c], 64*68
    float* Wq_s  = Wv_s + 64 * 68;        // [o][c] row-major, 64*68
    float* qhW_s = Wq_s + 64 * 68;        // [pt][h*68 + c], 8*544
    float* q_s   = qhW_s + 8 * 544;       // [pt][o], 512
    float* out_s = q_s + 512;             // [pt][o], 512
    float* pcd_s = out_s + 512;           // [nn][c] transposed, 8*68

    int t = threadIdx.x;
    for (int idx = t; idx < 64 * 67; idx += 256) {
        int o = idx / 67, c = idx % 67;
        WkT_s[c * 68 + o] = Wk[idx];
        Wv_s[o * 68 + c] = Wv[idx];
        Wq_s[o * 68 + c] = Wq[idx];
    }
    __syncthreads();

    const int pt = t >> 5, ln = t & 31, g = ln >> 2, kq = ln & 3;
    const int qo = t & 63, qp2 = t >> 6;          // q-projection mapping
    const int NTILE = (BB * NN) / 8;              // 8192

    for (int tile = blockIdx.x; tile < NTILE; tile += gridDim.x) {
        int b = (tile * 8) >> 14;
        int n0 = (tile * 8) & (NN - 1);

        // stage pcd_cat tile transposed: pcd_s[nn*68 + c]
        for (int idx = t; idx < 536; idx += 256) {
            int c = idx >> 3, nn = idx & 7;
            float v = (c < 64) ? pcd[(b * 64 + c) * NN + n0 + nn]
                               : xyz[(b * 3 + (c - 64)) * NN + n0 + nn];
            pcd_s[nn * 68 + c] = v;
        }
        __syncthreads();

        // q[pt][o] = sum_c Wq[o,c] * pcd_cat[c, n0+pt]; each thread does 2 pts (vectorized)
        {
            float a0 = 0.f, a1 = 0.f;
            const float* wr = Wq_s + qo * 68;
            const float* p0 = pcd_s + (2 * qp2) * 68;
            const float* p1 = p0 + 68;
            #pragma unroll
            for (int k4 = 0; k4 < 16; k4++) {
                float4 w = *(const float4*)(wr + 4 * k4);
                float4 x0 = *(const float4*)(p0 + 4 * k4);
                float4 x1 = *(const float4*)(p1 + 4 * k4);
                a0 += w.x * x0.x + w.y * x0.y + w.z * x0.z + w.w * x0.w;
                a1 += w.x * x1.x + w.y * x1.y + w.z * x1.z + w.w * x1.w;
            }
            #pragma unroll
            for (int c = 64; c < 67; c++) {
                float w = wr[c];
                a0 += w * p0[c];
                a1 += w * p1[c];
            }
            q_s[(2 * qp2) * 64 + qo] = a0;
            q_s[(2 * qp2 + 1) * 64 + qo] = a1;
        }
        __syncthreads();

        // qhW[h][c] = (1/sqrt(8)) * sum_d q[h*8+d] * Wk[h*8+d][c]
        {
            int h = ln & 7, c0 = ln >> 3;
            const float* qp = q_s + pt * 64 + h * 8;
            float4 qa = *(const float4*)qp;
            float4 qb = *(const float4*)(qp + 4);
            float* dst = qhW_s + pt * 544 + h * 68;
            for (int c = c0; c < 67; c += 4) {
                const float* wp = WkT_s + c * 68 + h * 8;
                float4 wa = *(const float4*)wp;
                float4 wb = *(const float4*)(wp + 4);
                float a = qa.x * wa.x + qa.y * wa.y + qa.z * wa.z + qa.w * wa.w
                        + qb.x * wb.x + qb.y * wb.y + qb.z * wb.z + qb.w * wb.w;
                dst[c] = a * 0.35355339059327373f;   // 1/sqrt(D)
            }
        }
        __syncwarp();

        int n = n0 + pt;

        // load neighbor block: 8 rows (c) x 4 cols (kk) per lane
        float4 nbv[8];
        {
            const float* nbase = neighbors + ((b * 64) * NN + n) * 16 + kq * 4;
            #pragma unroll
            for (int j = 0; j < 8; j++)
                nbv[j] = *(const float4*)(nbase + (g * 8 + j) * (NN * 16));
        }
        // gathered xyz: only lanes 0-3 (g==0) consume it
        float4 xr0 = make_float4(0.f, 0.f, 0.f, 0.f), xr1 = xr0, xr2 = xr0;
        if (ln < 4) {
            const int4 iv = *(const int4*)(idx_all + (b * NN + n) * 16 + ln * 4);
            const float* xb = xyz + b * 3 * NN;
            xr0 = make_float4(xb[iv.x], xb[iv.y], xb[iv.z], xb[iv.w]);
            xr1 = make_float4(xb[NN + iv.x], xb[NN + iv.y], xb[NN + iv.z], xb[NN + iv.w]);
            xr2 = make_float4(xb[2 * NN + iv.x], xb[2 * NN + iv.y], xb[2 * NN + iv.z], xb[2 * NN + iv.w]);
        }

        const float* qhWp = qhW_s + pt * 544;
        #pragma unroll 1
        for (int h = 0; h < 8; h++) {
            const float* qp = qhWp + h * 68;
            float4 qa = *(const float4*)(qp + g * 8);
            float4 qb = *(const float4*)(qp + g * 8 + 4);
            // energy partials over this lane's 8 channels
            float4 e = make_float4(0.f, 0.f, 0.f, 0.f);
            float qs[8] = {qa.x, qa.y, qa.z, qa.w, qb.x, qb.y, qb.z, qb.w};
            #pragma unroll
            for (int j = 0; j < 8; j++) {
                e.x += qs[j] * nbv[j].x; e.y += qs[j] * nbv[j].y;
                e.z += qs[j] * nbv[j].z; e.w += qs[j] * nbv[j].w;
            }
            if (g == 0) {   // xyz channels 64..66 counted once
                float4 qc = *(const float4*)(qp + 64);
                e.x += qc.x * xr0.x + qc.y * xr1.x + qc.z * xr2.x;
                e.y += qc.x * xr0.y + qc.y * xr1.y + qc.z * xr2.y;
                e.z += qc.x * xr0.z + qc.y * xr1.z + qc.z * xr2.z;
                e.w += qc.x * xr0.w + qc.y * xr1.w + qc.z * xr2.w;
            }
            // reduce over g (xor 4,8,16)
            #pragma unroll
            for (int m = 4; m <= 16; m <<= 1) {
                e.x += __shfl_xor_sync(0xffffffffu, e.x, m);
                e.y += __shfl_xor_sync(0xffffffffu, e.y, m);
                e.z += __shfl_xor_sync(0xffffffffu, e.z, m);
                e.w += __shfl_xor_sync(0xffffffffu, e.w, m);
            }
            // softmax over the 16 kk, no max-subtraction (|e| bounded ~4)
            float4 pr;
            pr.x = __expf(e.x); pr.y = __expf(e.y);
            pr.z = __expf(e.z); pr.w = __expf(e.w);
            float s = pr.x + pr.y + pr.z + pr.w;
            s += __shfl_xor_sync(0xffffffffu, s, 1);
            s += __shfl_xor_sync(0xffffffffu, s, 2);
            float inv = __fdividef(1.0f, s);   // applied at output (linear)

            // s[c] partials (dot of unnormalized attn with this lane's 4 kk)
            float sp[8];
            #pragma unroll
            for (int j = 0; j < 8; j++)
                sp[j] = pr.x * nbv[j].x + pr.y * nbv[j].y + pr.z * nbv[j].z + pr.w * nbv[j].w;
            #pragma unroll
            for (int j = 0; j < 8; j++) {
                sp[j] += __shfl_xor_sync(0xffffffffu, sp[j], 1);
                sp[j] += __shfl_xor_sync(0xffffffffu, sp[j], 2);
            }
            // xyz-channel s values: only lanes 0-3 produce/consume (xor 1,2 closed there)
            float sx0 = pr.x * xr0.x + pr.y * xr0.y + pr.z * xr0.z + pr.w * xr0.w;
            float sx1 = pr.x * xr1.x + pr.y * xr1.y + pr.z * xr1.z + pr.w * xr1.w;
            float sx2 = pr.x * xr2.x + pr.y * xr2.y + pr.z * xr2.z + pr.w * xr2.w;
            sx0 += __shfl_xor_sync(0xffffffffu, sx0, 1);
            sx0 += __shfl_xor_sync(0xffffffffu, sx0, 2);
            sx1 += __shfl_xor_sync(0xffffffffu, sx1, 1);
            sx1 += __shfl_xor_sync(0xffffffffu, sx1, 2);
            sx2 += __shfl_xor_sync(0xffffffffu, sx2, 1);
            sx2 += __shfl_xor_sync(0xffffffffu, sx2, 2);

            // out[o] = inv * sum_c Wv[o][c] * s[c]; kq picks d-pair, g picks c-chunk
            #pragma unroll
            for (int dd = 0; dd < 2; dd++) {
                int o = h * 8 + kq * 2 + dd;
                const float* wp = Wv_s + o * 68;
                float4 wa = *(const float4*)(wp + g * 8);
                float4 wb = *(const float4*)(wp + g * 8 + 4);
                float a = wa.x * sp[0] + wa.y * sp[1] + wa.z * sp[2] + wa.w * sp[3]
                        + wb.x * sp[4] + wb.y * sp[5] + wb.z * sp[6] + wb.w * sp[7];
                if (g == 0) {
                    float4 wc = *(const float4*)(wp + 64);
                    a += wc.x * sx0 + wc.y * sx1 + wc.z * sx2;
                }
                a += __shfl_xor_sync(0xffffffffu, a, 4);
                a += __shfl_xor_sync(0xffffffffu, a, 8);
                a += __shfl_xor_sync(0xffffffffu, a, 16);
                if (ln < 4) out_s[pt * 64 + o] = a * inv;
            }
        }
        __syncthreads();
        // coalesced output: out[b][o][n]
        for (int idx = t; idx < 512; idx += 256) {
            int o = idx >> 3, lpt = idx & 7;
            out[(b * 64 + o) * NN + n0 + lpt] = out_s[lpt * 64 + o];
        }
        // no trailing barrier: next iteration's leading barriers order out_s reuse
    }
}

extern "C" void kernel_launch(void* const* d_in, const int* in_sizes, int n_in,
                              void* d_out, int out_size) {
    const float* pcd       = (const float*)d_in[0];
    const float* neighbors = (const float*)d_in[1];
    const float* xyz       = (const float*)d_in[2];
    const float* Wq        = (const float*)d_in[3];
    const float* Wk        = (const float*)d_in[4];
    const float* Wv        = (const float*)d_in[5];
    const int*   idx_all   = (const int*)d_in[6];
    float* out = (float*)d_out;

    // floats: WkT 4556 + Wv 4352 + Wq 4352 + qhW 4352 + q 512 + out 512 + pcd 544
    const int smem = (67 * 68 + 64 * 68 + 64 * 68 + 8 * 544 + 512 + 512 + 544) * 4;
    cudaFuncSetAttribute(attn_kernel, cudaFuncAttributeMaxDynamicSharedMemorySize, smem);
    attn_kernel<<<304, 256, smem>>>(pcd, neighbors, xyz, Wq, Wk, Wv, idx_all, out);
}